// round 9
// baseline (speedup 1.0000x reference)
#include <cuda_runtime.h>
#include <cstdint>
#include <cstddef>

#define B_   4
#define T_   1024
#define H_   32
#define KVH_ 8
#define HD_  128
#define DM_  4096
#define NTOK (B_ * T_)
#define KDIM 4096

// ---------------------------------------------------------------------------
// Scratch (device globals — no runtime allocation allowed)
// ---------------------------------------------------------------------------
__device__ float g_x  [(size_t)NTOK * DM_];    // rna(x)
__device__ float g_wqT [(size_t)DM_ * DM_];    // rna(w_q)^T  [N][K]
__device__ float g_wkvT[(size_t)2048 * DM_];   // rna(w_kv)^T [N][K]
__device__ float g_woT [(size_t)DM_ * DM_];    // rna(w_o)^T  [N][K]
__device__ float g_q  [(size_t)NTOK * DM_];    // q after proj+rope (rna)
__device__ float g_kv [(size_t)NTOK * 2048];   // [n][ k(8*128) | v(8*128) ] (rna)
__device__ float g_att[(size_t)NTOK * DM_];    // attention out (rna)

// ---------------------------------------------------------------------------
// helpers
// ---------------------------------------------------------------------------
__device__ __forceinline__ uint32_t f2tf(float x) {
    uint32_t r;
    asm("cvt.rna.tf32.f32 %0, %1;" : "=r"(r) : "f"(x));
    return r;
}

__device__ __forceinline__ uint32_t smem_u32(const void* p) {
    uint32_t a;
    asm("{ .reg .u64 t; cvta.to.shared.u64 t, %1; cvt.u32.u64 %0, t; }"
        : "=r"(a) : "l"(p));
    return a;
}

__device__ __forceinline__ void cp_async16(uint32_t dst, const float* src) {
    asm volatile("cp.async.cg.shared.global [%0], [%1], 16;\n"
                 :: "r"(dst), "l"(src) : "memory");
}
#define CP_COMMIT() asm volatile("cp.async.commit_group;\n" ::: "memory")
#define CP_WAIT(n)  asm volatile("cp.async.wait_group %0;\n" :: "n"(n) : "memory")

__device__ __forceinline__ void mma_tf32(float d[4], const uint32_t a[4],
                                         uint32_t b0, uint32_t b1) {
    asm volatile(
        "mma.sync.aligned.m16n8k8.row.col.f32.tf32.tf32.f32 "
        "{%0,%1,%2,%3}, {%4,%5,%6,%7}, {%8,%9}, {%0,%1,%2,%3};\n"
        : "+f"(d[0]), "+f"(d[1]), "+f"(d[2]), "+f"(d[3])
        : "r"(a[0]), "r"(a[1]), "r"(a[2]), "r"(a[3]), "r"(b0), "r"(b1));
}

// ---------------------------------------------------------------------------
// tf32 GEMM: C[M,N] = A[M,K] @ Bt[N,K]^T. A, Bt pre-rounded to tf32.
// Block 256x128, BK=32, **512 threads (16 warps, 8x2, warp tile 32x64)**.
// 4-stage cp.async pipeline. Both smem tiles K-major [outer][36].
// 4 warps/SMSP for latency hiding; L2 traffic identical to 256-thread ver.
// ---------------------------------------------------------------------------
#define BM 256
#define BN 128
#define BK 32
#define NST 4
#define TS 36                          // smem row stride (floats)
#define A_TILE_F (BM * TS)             // 9216 floats
#define B_TILE_F (BN * TS)             // 4608 floats
#define STG_F (A_TILE_F + B_TILE_F)    // 13824 floats = 55296 B
#define GEMM_SMEM (NST * STG_F * 4)    // 221184 B

__global__ void __launch_bounds__(512, 1)
gemm_tc(const float* __restrict__ A, const float* __restrict__ Bt,
        float* __restrict__ C, int N) {
    extern __shared__ float sm[];
    const uint32_t sbase = smem_u32(sm);

    const int tid  = threadIdx.x;
    const int warp = tid >> 5;
    const int lane = tid & 31;
    const int wm = warp & 7;           // M: 8 warps, 32 rows each
    const int wn = warp >> 3;          // N: 2 warps, 64 cols each
    const int gr = lane >> 2;
    const int tg = lane & 3;
    const int m0 = blockIdx.y * BM;
    const int n0 = blockIdx.x * BN;
    const int NK = KDIM / BK;

    const float* aseg = A  + (size_t)m0 * KDIM;
    const float* bseg = Bt + (size_t)n0 * KDIM;

    auto load_stage = [&](int s, int kt) {
        const uint32_t dst = sbase + (uint32_t)(s * STG_F) * 4u;
        const int kf = kt * BK;
        #pragma unroll
        for (int p = 0; p < 4; p++) {               // A: 2048 float4
            int i = tid + p * 512;
            int row = i >> 3, u = i & 7;
            cp_async16(dst + (uint32_t)(row * TS + u * 4) * 4u,
                       aseg + (size_t)row * KDIM + kf + u * 4);
        }
        const uint32_t dstB = dst + (uint32_t)A_TILE_F * 4u;
        #pragma unroll
        for (int p = 0; p < 2; p++) {               // B: 1024 float4
            int i = tid + p * 512;
            int row = i >> 3, u = i & 7;
            cp_async16(dstB + (uint32_t)(row * TS + u * 4) * 4u,
                       bseg + (size_t)row * KDIM + kf + u * 4);
        }
        CP_COMMIT();
    };

    float acc[2][8][4];
    #pragma unroll
    for (int mt = 0; mt < 2; mt++)
        #pragma unroll
        for (int nt = 0; nt < 8; nt++)
            #pragma unroll
            for (int e = 0; e < 4; e++) acc[mt][nt][e] = 0.f;

    for (int s = 0; s < NST - 1; s++) load_stage(s, s);

    for (int kt = 0; kt < NK; kt++) {
        if (kt + NST - 1 < NK) CP_WAIT(NST - 2); else CP_WAIT(0);
        __syncthreads();
        if (kt + NST - 1 < NK) load_stage((kt + NST - 1) % NST, kt + NST - 1);

        const float* As = sm + (size_t)(kt % NST) * STG_F;
        const float* Bs = As + A_TILE_F;
        const float* Aw = As + (wm * 32 + gr) * TS;
        const float* Bw = Bs + (wn * 64 + gr) * TS;

        #pragma unroll
        for (int ks = 0; ks < 4; ks++) {
            const int c0 = ks * 8 + tg;
            uint32_t af[2][4];
            #pragma unroll
            for (int mt = 0; mt < 2; mt++) {
                const float* ap = Aw + mt * 16 * TS;
                af[mt][0] = __float_as_uint(ap[c0]);
                af[mt][1] = __float_as_uint(ap[8 * TS + c0]);
                af[mt][2] = __float_as_uint(ap[c0 + 4]);
                af[mt][3] = __float_as_uint(ap[8 * TS + c0 + 4]);
            }
            #pragma unroll
            for (int nt = 0; nt < 8; nt++) {
                const float* bp = Bw + nt * 8 * TS;
                uint32_t b0 = __float_as_uint(bp[c0]);
                uint32_t b1 = __float_as_uint(bp[c0 + 4]);
                #pragma unroll
                for (int mt = 0; mt < 2; mt++)
                    mma_tf32(acc[mt][nt], af[mt], b0, b1);
            }
        }
        __syncthreads();
    }

    #pragma unroll
    for (int mt = 0; mt < 2; mt++) {
        #pragma unroll
        for (int e2 = 0; e2 < 2; e2++) {
            int row = m0 + wm * 32 + mt * 16 + gr + e2 * 8;
            float* crow = C + (size_t)row * N + n0 + wn * 64;
            #pragma unroll
            for (int nt = 0; nt < 8; nt++) {
                float2 v;
                v.x = acc[mt][nt][e2 * 2];
                v.y = acc[mt][nt][e2 * 2 + 1];
                *(float2*)(crow + nt * 8 + 2 * tg) = v;
            }
        }
    }
}

// ---------------------------------------------------------------------------
// prep kernels
// ---------------------------------------------------------------------------
__global__ void round_x_kernel(const float* __restrict__ in, float* __restrict__ out,
                               int n4) {
    int i = blockIdx.x * blockDim.x + threadIdx.x;
    if (i >= n4) return;
    float4 v = ((const float4*)in)[i];
    v.x = __uint_as_float(f2tf(v.x));
    v.y = __uint_as_float(f2tf(v.y));
    v.z = __uint_as_float(f2tf(v.z));
    v.w = __uint_as_float(f2tf(v.w));
    ((float4*)out)[i] = v;
}

__global__ void transpose_rna_kernel(const float* __restrict__ W, float* __restrict__ Wt,
                                     int rows /*K*/, int cols /*N*/) {
    __shared__ float t[32][33];
    int bx = blockIdx.x * 32;
    int by = blockIdx.y * 32;
    int lx = threadIdx.x, ly = threadIdx.y;   // 32 x 8
    #pragma unroll
    for (int i = 0; i < 32; i += 8)
        t[ly + i][lx] = W[(size_t)(by + ly + i) * cols + bx + lx];
    __syncthreads();
    #pragma unroll
    for (int i = 0; i < 32; i += 8)
        Wt[(size_t)(bx + ly + i) * rows + by + lx] =
            __uint_as_float(f2tf(t[lx][ly + i]));
}

__global__ void round_v_kernel(float* __restrict__ kv) {
    int i = blockIdx.x * blockDim.x + threadIdx.x;   // float4 index
    if (i >= NTOK * 256) return;
    int n = i >> 8, c4 = i & 255;
    float4* p = (float4*)(kv + (size_t)n * 2048 + 1024 + c4 * 4);
    float4 v = *p;
    v.x = __uint_as_float(f2tf(v.x));
    v.y = __uint_as_float(f2tf(v.y));
    v.z = __uint_as_float(f2tf(v.z));
    v.w = __uint_as_float(f2tf(v.w));
    *p = v;
}

// ---------------------------------------------------------------------------
// RoPE (in place, writes rna-rounded)
// ---------------------------------------------------------------------------
__global__ void rope_kernel(float* __restrict__ buf, const float* __restrict__ rcos,
                            const float* __restrict__ rsin,
                            const int* __restrict__ positions,
                            int nheads, int rowstride) {
    int idx = blockIdx.x * blockDim.x + threadIdx.x;
    int total = NTOK * nheads * 64;
    if (idx >= total) return;
    int i = idx & 63;
    int h = (idx >> 6) % nheads;
    int n = idx / (64 * nheads);
    int pos = positions[n];
    float c = rcos[pos * 64 + i];
    float s = rsin[pos * 64 + i];
    float2* p = (float2*)(buf + (size_t)n * rowstride + h * 128 + 2 * i);
    float2 v = *p;
    float2 o;
    o.x = __uint_as_float(f2tf(v.x * c - v.y * s));
    o.y = __uint_as_float(f2tf(v.x * s + v.y * c));
    *p = o;
}

// ---------------------------------------------------------------------------
// Flash attention, causal, GQA, tf32 mma. All inputs pre-rounded to tf32.
// grid = (T/64, H, nb), block = 128 (4 warps). b = b_off + blockIdx.z.
// Longest causal tiles scheduled first. smem 101KB -> 2 CTAs/SM.
// ---------------------------------------------------------------------------
#define ATT_SMEM_FLOATS (3 * 64 * 132)

__global__ void __launch_bounds__(128)
attn_kernel(const float* __restrict__ q, const float* __restrict__ kv,
            float* __restrict__ out, int b_off) {
    extern __shared__ float sm[];
    float* Ks = sm;
    float* Vs = sm + 64 * 132;
    float* Qs = sm + 2 * 64 * 132;
    float* Ps = Qs;                    // alias: safe (per-warp rows)
    const uint32_t sK = smem_u32(Ks);
    const uint32_t sV = smem_u32(Vs);

    const int mblk = gridDim.x - 1 - blockIdx.x;   // longest tiles first
    const int m0  = mblk * 64;
    const int h   = blockIdx.y;
    const int b   = b_off + blockIdx.z;
    const int kvh = h >> 2;
    const int tid  = threadIdx.x;
    const int warp = tid >> 5;
    const int lane = tid & 31;
    const int gr = lane >> 2;
    const int tg = lane & 3;

    for (int i = tid; i < 64 * 32; i += 128) {
        int r = i >> 5, c4 = i & 31;
        float4 v = *(const float4*)&q[((size_t)(b * T_ + m0 + r) * H_ + h) * HD_ + c4 * 4];
        *(float4*)&Qs[r * 132 + c4 * 4] = v;
    }
    __syncthreads();

    uint32_t qf[16][4];
    #pragma unroll
    for (int ks = 0; ks < 16; ks++) {
        int r0 = warp * 16 + gr;
        int c0 = ks * 8 + tg;
        qf[ks][0] = __float_as_uint(Qs[r0 * 132 + c0]);
        qf[ks][1] = __float_as_uint(Qs[(r0 + 8) * 132 + c0]);
        qf[ks][2] = __float_as_uint(Qs[r0 * 132 + c0 + 4]);
        qf[ks][3] = __float_as_uint(Qs[(r0 + 8) * 132 + c0 + 4]);
    }

    float o_acc[16][4];
    #pragma unroll
    for (int nt = 0; nt < 16; nt++)
        #pragma unroll
        for (int e = 0; e < 4; e++) o_acc[nt][e] = 0.f;
    float m_i[2] = {-INFINITY, -INFINITY};
    float l_i[2] = {0.f, 0.f};

    const float scale = 0.08838834764831845f;
    const int ktiles = m0 / 64 + 1;

    for (int kt = 0; kt < ktiles; kt++) {
        int k0 = kt * 64;
        __syncthreads();
        {
            const float* base = &kv[(size_t)(b * T_ + k0) * 2048 + kvh * 128];
            #pragma unroll
            for (int p = 0; p < 16; p++) {
                int i = tid + p * 128;
                int r = i >> 5, c4 = i & 31;
                uint32_t soff = (uint32_t)(r * 132 + c4 * 4) * 4u;
                const float* kp = base + (size_t)r * 2048;
                cp_async16(sK + soff, kp + c4 * 4);
                cp_async16(sV + soff, kp + 1024 + c4 * 4);
            }
            CP_COMMIT();
            CP_WAIT(0);
        }
        __syncthreads();

        float s[8][4];
        #pragma unroll
        for (int nt = 0; nt < 8; nt++)
            #pragma unroll
            for (int e = 0; e < 4; e++) s[nt][e] = 0.f;

        #pragma unroll 4
        for (int ks = 0; ks < 16; ks++) {
            #pragma unroll
            for (int nt = 0; nt < 8; nt++) {
                int cc = nt * 8 + gr;
                int rr = ks * 8 + tg;
                uint32_t b0 = __float_as_uint(Ks[cc * 132 + rr]);
                uint32_t b1 = __float_as_uint(Ks[cc * 132 + rr + 4]);
                mma_tf32(s[nt], qf[ks], b0, b1);
            }
        }

        bool diag = (kt == ktiles - 1);
        #pragma unroll
        for (int nt = 0; nt < 8; nt++)
            #pragma unroll
            for (int e = 0; e < 4; e++) {
                int row = warp * 16 + gr + ((e >= 2) ? 8 : 0);
                int col = nt * 8 + 2 * tg + (e & 1);
                float v = s[nt][e] * scale;
                if (diag && (k0 + col > m0 + row)) v = -1e9f;
                s[nt][e] = v;
            }

        #pragma unroll
        for (int half = 0; half < 2; half++) {
            float mx = -INFINITY;
            #pragma unroll
            for (int nt = 0; nt < 8; nt++) {
                mx = fmaxf(mx, s[nt][half * 2]);
                mx = fmaxf(mx, s[nt][half * 2 + 1]);
            }
            mx = fmaxf(mx, __shfl_xor_sync(0xffffffffu, mx, 1));
            mx = fmaxf(mx, __shfl_xor_sync(0xffffffffu, mx, 2));
            float mnew = fmaxf(m_i[half], mx);
            float corr = __expf(m_i[half] - mnew);
            float lsum = 0.f;
            #pragma unroll
            for (int nt = 0; nt < 8; nt++) {
                float e0 = __expf(s[nt][half * 2]     - mnew);
                float e1 = __expf(s[nt][half * 2 + 1] - mnew);
                s[nt][half * 2]     = e0;
                s[nt][half * 2 + 1] = e1;
                lsum += e0 + e1;
            }
            lsum += __shfl_xor_sync(0xffffffffu, lsum, 1);
            lsum += __shfl_xor_sync(0xffffffffu, lsum, 2);
            m_i[half] = mnew;
            l_i[half] = l_i[half] * corr + lsum;
            #pragma unroll
            for (int nt = 0; nt < 16; nt++) {
                o_acc[nt][half * 2]     *= corr;
                o_acc[nt][half * 2 + 1] *= corr;
            }
        }

        #pragma unroll
        for (int nt = 0; nt < 8; nt++)
            #pragma unroll
            for (int e = 0; e < 4; e++) {
                int row = warp * 16 + gr + ((e >= 2) ? 8 : 0);
                int col = nt * 8 + 2 * tg + (e & 1);
                Ps[row * 132 + col] = __uint_as_float(f2tf(s[nt][e]));
            }
        __syncwarp();

        #pragma unroll
        for (int ks = 0; ks < 8; ks++) {
            uint32_t pa[4];
            int r0 = warp * 16 + gr;
            int c0 = ks * 8 + tg;
            pa[0] = __float_as_uint(Ps[r0 * 132 + c0]);
            pa[1] = __float_as_uint(Ps[(r0 + 8) * 132 + c0]);
            pa[2] = __float_as_uint(Ps[r0 * 132 + c0 + 4]);
            pa[3] = __float_as_uint(Ps[(r0 + 8) * 132 + c0 + 4]);
            #pragma unroll
            for (int nt = 0; nt < 16; nt++) {
                uint32_t b0 = __float_as_uint(Vs[(ks * 8 + tg) * 132 + nt * 8 + gr]);
                uint32_t b1 = __float_as_uint(Vs[(ks * 8 + tg + 4) * 132 + nt * 8 + gr]);
                mma_tf32(o_acc[nt], pa, b0, b1);
            }
        }
    }

    #pragma unroll
    for (int nt = 0; nt < 16; nt++)
        #pragma unroll
        for (int e = 0; e < 4; e++) {
            int row = warp * 16 + gr + ((e >= 2) ? 8 : 0);
            int col = nt * 8 + 2 * tg + (e & 1);
            float inv_l = 1.f / l_i[(e >= 2) ? 1 : 0];
            out[((size_t)(b * T_ + m0 + row) * H_ + h) * HD_ + col] =
                __uint_as_float(f2tf(o_acc[nt][e] * inv_l));
        }
}

// ---------------------------------------------------------------------------
// launch — serial prep chain (launches 0-3), then gemm fork at indices 4/5
// (guarantees ncu -s 5 captures gemm_tc), then attn/O-GEMM split pipeline.
// ---------------------------------------------------------------------------
extern "C" void kernel_launch(void* const* d_in, const int* in_sizes, int n_in,
                              void* d_out, int out_size) {
    const float* x    = (const float*)d_in[0];
    const float* w_q  = (const float*)d_in[1];
    const float* w_kv = (const float*)d_in[2];
    const float* w_o  = (const float*)d_in[3];
    const float* rcos = (const float*)d_in[6];
    const float* rsin = (const float*)d_in[7];
    const int* positions = (const int*)d_in[8];
    float* out = (float*)d_out;

    float *xb, *wqT, *wkvT, *woT, *qb, *kvb, *ab;
    cudaGetSymbolAddress((void**)&xb,   g_x);
    cudaGetSymbolAddress((void**)&wqT,  g_wqT);
    cudaGetSymbolAddress((void**)&wkvT, g_wkvT);
    cudaGetSymbolAddress((void**)&woT,  g_woT);
    cudaGetSymbolAddress((void**)&qb,   g_q);
    cudaGetSymbolAddress((void**)&kvb,  g_kv);
    cudaGetSymbolAddress((void**)&ab,   g_att);

    static cudaStream_t s1 = nullptr;
    static cudaEvent_t ev_prep = nullptr, ev_kv = nullptr, ev_q = nullptr,
                       ev_a0 = nullptr, ev_o0 = nullptr;
    if (s1 == nullptr) {
        cudaStreamCreateWithFlags(&s1, cudaStreamNonBlocking);
        cudaEventCreateWithFlags(&ev_prep, cudaEventDisableTiming);
        cudaEventCreateWithFlags(&ev_kv,   cudaEventDisableTiming);
        cudaEventCreateWithFlags(&ev_q,    cudaEventDisableTiming);
        cudaEventCreateWithFlags(&ev_a0,   cudaEventDisableTiming);
        cudaEventCreateWithFlags(&ev_o0,   cudaEventDisableTiming);
        cudaFuncSetAttribute(gemm_tc,
            cudaFuncAttributeMaxDynamicSharedMemorySize, GEMM_SMEM);
        cudaFuncSetAttribute(attn_kernel,
            cudaFuncAttributeMaxDynamicSharedMemorySize, ATT_SMEM_FLOATS * 4);
    }

    // serial prep chain on s0: launches 0..3
    round_x_kernel<<<(NTOK * DM_ / 4 + 255) / 256, 256>>>(x, xb, NTOK * DM_ / 4);
    transpose_rna_kernel<<<dim3(DM_ / 32, DM_ / 32), dim3(32, 8)>>>(w_q, wqT, DM_, DM_);
    transpose_rna_kernel<<<dim3(2048 / 32, DM_ / 32), dim3(32, 8)>>>(w_kv, wkvT, DM_, 2048);
    transpose_rna_kernel<<<dim3(DM_ / 32, DM_ / 32), dim3(32, 8)>>>(w_o, woT, DM_, DM_);
    cudaEventRecord(ev_prep, 0);

    // fork: gemm_kv on s1 (launch 4), gemm_q on s0 (launch 5 — ncu target)
    cudaStreamWaitEvent(s1, ev_prep, 0);
    gemm_tc<<<dim3(2048 / BN, NTOK / BM), 512, GEMM_SMEM, s1>>>(xb, wkvT, kvb, 2048);
    rope_kernel<<<(NTOK * KVH_ * 64) / 256, 256, 0, s1>>>(kvb, rcos, rsin, positions, KVH_, 2048);
    round_v_kernel<<<(NTOK * 256 + 255) / 256, 256, 0, s1>>>(kvb);
    cudaEventRecord(ev_kv, s1);

    gemm_tc<<<dim3(DM_ / BN, NTOK / BM), 512, GEMM_SMEM>>>(xb, wqT, qb, DM_);
    rope_kernel<<<(NTOK * H_ * 64) / 256, 256>>>(qb, rcos, rsin, positions, H_, DM_);

    // attention: needs q (s0 chain) + kv (s1 chain)
    cudaStreamWaitEvent(0, ev_kv, 0);
    attn_kernel<<<dim3(T_ / 64, H_, 2), 128, ATT_SMEM_FLOATS * 4>>>(qb, kvb, ab, 0);
    cudaEventRecord(ev_a0, 0);
    attn_kernel<<<dim3(T_ / 64, H_, 2), 128, ATT_SMEM_FLOATS * 4>>>(qb, kvb, ab, 2);

    // O-projection half 0 on s1 overlapping attention half 1
    cudaStreamWaitEvent(s1, ev_a0, 0);
    gemm_tc<<<dim3(DM_ / BN, (NTOK / 2) / BM), 512, GEMM_SMEM, s1>>>(
        ab, woT, out, DM_);
    cudaEventRecord(ev_o0, s1);

    // O-projection half 1 on s0, then join
    gemm_tc<<<dim3(DM_ / BN, (NTOK / 2) / BM), 512, GEMM_SMEM>>>(
        ab + (size_t)(NTOK / 2) * DM_, woT, out + (size_t)(NTOK / 2) * DM_, DM_);
    cudaStreamWaitEvent(0, ev_o0, 0);
}

// round 10
// speedup vs baseline: 1.1039x; 1.1039x over previous
#include <cuda_runtime.h>
#include <cstdint>
#include <cstddef>

#define B_   4
#define T_   1024
#define H_   32
#define KVH_ 8
#define HD_  128
#define DM_  4096
#define NTOK (B_ * T_)
#define KDIM 4096

// ---------------------------------------------------------------------------
// Scratch (device globals — no runtime allocation allowed)
// ---------------------------------------------------------------------------
__device__ float g_x  [(size_t)NTOK * DM_];    // rna(x)
__device__ float g_wqT [(size_t)DM_ * DM_];    // rna(w_q)^T  [N][K]
__device__ float g_wkvT[(size_t)2048 * DM_];   // rna(w_kv)^T [N][K]
__device__ float g_woT [(size_t)DM_ * DM_];    // rna(w_o)^T  [N][K]
__device__ float g_q  [(size_t)NTOK * DM_];    // q after proj+rope (rna)
__device__ float g_kv [(size_t)NTOK * 2048];   // [n][ k(8*128) | v(8*128) ] (rna)
__device__ float g_att[(size_t)NTOK * DM_];    // attention out (rna)

// ---------------------------------------------------------------------------
// helpers
// ---------------------------------------------------------------------------
__device__ __forceinline__ uint32_t f2tf(float x) {
    uint32_t r;
    asm("cvt.rna.tf32.f32 %0, %1;" : "=r"(r) : "f"(x));
    return r;
}

__device__ __forceinline__ uint32_t smem_u32(const void* p) {
    uint32_t a;
    asm("{ .reg .u64 t; cvta.to.shared.u64 t, %1; cvt.u32.u64 %0, t; }"
        : "=r"(a) : "l"(p));
    return a;
}

__device__ __forceinline__ void cp_async16(uint32_t dst, const float* src) {
    asm volatile("cp.async.cg.shared.global [%0], [%1], 16;\n"
                 :: "r"(dst), "l"(src) : "memory");
}
#define CP_COMMIT() asm volatile("cp.async.commit_group;\n" ::: "memory")
#define CP_WAIT(n)  asm volatile("cp.async.wait_group %0;\n" :: "n"(n) : "memory")

__device__ __forceinline__ void mma_tf32(float d[4], const uint32_t a[4],
                                         uint32_t b0, uint32_t b1) {
    asm volatile(
        "mma.sync.aligned.m16n8k8.row.col.f32.tf32.tf32.f32 "
        "{%0,%1,%2,%3}, {%4,%5,%6,%7}, {%8,%9}, {%0,%1,%2,%3};\n"
        : "+f"(d[0]), "+f"(d[1]), "+f"(d[2]), "+f"(d[3])
        : "r"(a[0]), "r"(a[1]), "r"(a[2]), "r"(a[3]), "r"(b0), "r"(b1));
}

// ---------------------------------------------------------------------------
// tf32 GEMM: C[M,N] = A[M,K] @ Bt[N,K]^T. A, Bt pre-rounded to tf32.
// Block 256x128, **BK=64**, 256 threads (8 warps, 4x2), warp tile 64x64.
// **2-stage** cp.async double-buffer: half the iterations/barriers of BK=32.
// smem tiles K-major [outer][68] (conflict-free fragment LDS).
// ---------------------------------------------------------------------------
#define BM 256
#define BN 128
#define BK 64
#define NST 2
#define TS 68                          // smem row stride (floats)
#define A_TILE_F (BM * TS)             // 17408 floats
#define B_TILE_F (BN * TS)             // 8704 floats
#define STG_F (A_TILE_F + B_TILE_F)    // 26112 floats = 104448 B
#define GEMM_SMEM (NST * STG_F * 4)    // 208896 B

__global__ void __launch_bounds__(256, 1)
gemm_tc(const float* __restrict__ A, const float* __restrict__ Bt,
        float* __restrict__ C, int N) {
    extern __shared__ float sm[];
    const uint32_t sbase = smem_u32(sm);

    const int tid  = threadIdx.x;
    const int warp = tid >> 5;
    const int lane = tid & 31;
    const int wm = warp & 3;           // M: 4 warps, 64 rows each
    const int wn = warp >> 2;          // N: 2 warps, 64 cols each
    const int gr = lane >> 2;
    const int tg = lane & 3;
    const int m0 = blockIdx.y * BM;
    const int n0 = blockIdx.x * BN;
    const int NK = KDIM / BK;          // 64 iterations

    const float* aseg = A  + (size_t)m0 * KDIM;
    const float* bseg = Bt + (size_t)n0 * KDIM;

    auto load_stage = [&](int s, int kt) {
        const uint32_t dst = sbase + (uint32_t)(s * STG_F) * 4u;
        const int kf = kt * BK;
        #pragma unroll
        for (int p = 0; p < 16; p++) {              // A: 4096 float4
            int i = tid + p * 256;
            int row = i >> 4, u = i & 15;
            cp_async16(dst + (uint32_t)(row * TS + u * 4) * 4u,
                       aseg + (size_t)row * KDIM + kf + u * 4);
        }
        const uint32_t dstB = dst + (uint32_t)A_TILE_F * 4u;
        #pragma unroll
        for (int p = 0; p < 8; p++) {               // B: 2048 float4
            int i = tid + p * 256;
            int row = i >> 4, u = i & 15;
            cp_async16(dstB + (uint32_t)(row * TS + u * 4) * 4u,
                       bseg + (size_t)row * KDIM + kf + u * 4);
        }
        CP_COMMIT();
    };

    float acc[4][8][4];
    #pragma unroll
    for (int mt = 0; mt < 4; mt++)
        #pragma unroll
        for (int nt = 0; nt < 8; nt++)
            #pragma unroll
            for (int e = 0; e < 4; e++) acc[mt][nt][e] = 0.f;

    load_stage(0, 0);

    for (int kt = 0; kt < NK; kt++) {
        if (kt + 1 < NK) {
            load_stage((kt + 1) & 1, kt + 1);  // prefetch next buffer
            CP_WAIT(1);                        // current stage landed
        } else {
            CP_WAIT(0);
        }
        __syncthreads();

        const float* As = sm + (size_t)(kt & 1) * STG_F;
        const float* Bs = As + A_TILE_F;
        const float* Aw = As + (wm * 64 + gr) * TS;
        const float* Bw = Bs + (wn * 64 + gr) * TS;

        #pragma unroll
        for (int ks = 0; ks < 8; ks++) {
            const int c0 = ks * 8 + tg;
            uint32_t af[4][4];
            #pragma unroll
            for (int mt = 0; mt < 4; mt++) {
                const float* ap = Aw + mt * 16 * TS;
                af[mt][0] = __float_as_uint(ap[c0]);
                af[mt][1] = __float_as_uint(ap[8 * TS + c0]);
                af[mt][2] = __float_as_uint(ap[c0 + 4]);
                af[mt][3] = __float_as_uint(ap[8 * TS + c0 + 4]);
            }
            #pragma unroll
            for (int nt = 0; nt < 8; nt++) {
                const float* bp = Bw + nt * 8 * TS;
                uint32_t b0 = __float_as_uint(bp[c0]);
                uint32_t b1 = __float_as_uint(bp[c0 + 4]);
                #pragma unroll
                for (int mt = 0; mt < 4; mt++)
                    mma_tf32(acc[mt][nt], af[mt], b0, b1);
            }
        }
        __syncthreads();   // compute done before next iter overwrites this buf
    }

    #pragma unroll
    for (int mt = 0; mt < 4; mt++) {
        #pragma unroll
        for (int e2 = 0; e2 < 2; e2++) {
            int row = m0 + wm * 64 + mt * 16 + gr + e2 * 8;
            float* crow = C + (size_t)row * N + n0 + wn * 64;
            #pragma unroll
            for (int nt = 0; nt < 8; nt++) {
                float2 v;
                v.x = acc[mt][nt][e2 * 2];
                v.y = acc[mt][nt][e2 * 2 + 1];
                *(float2*)(crow + nt * 8 + 2 * tg) = v;
            }
        }
    }
}

// ---------------------------------------------------------------------------
// prep kernels
// ---------------------------------------------------------------------------
__global__ void round_x_kernel(const float* __restrict__ in, float* __restrict__ out,
                               int n4) {
    int i = blockIdx.x * blockDim.x + threadIdx.x;
    if (i >= n4) return;
    float4 v = ((const float4*)in)[i];
    v.x = __uint_as_float(f2tf(v.x));
    v.y = __uint_as_float(f2tf(v.y));
    v.z = __uint_as_float(f2tf(v.z));
    v.w = __uint_as_float(f2tf(v.w));
    ((float4*)out)[i] = v;
}

__global__ void transpose_rna_kernel(const float* __restrict__ W, float* __restrict__ Wt,
                                     int rows /*K*/, int cols /*N*/) {
    __shared__ float t[32][33];
    int bx = blockIdx.x * 32;
    int by = blockIdx.y * 32;
    int lx = threadIdx.x, ly = threadIdx.y;   // 32 x 8
    #pragma unroll
    for (int i = 0; i < 32; i += 8)
        t[ly + i][lx] = W[(size_t)(by + ly + i) * cols + bx + lx];
    __syncthreads();
    #pragma unroll
    for (int i = 0; i < 32; i += 8)
        Wt[(size_t)(bx + ly + i) * rows + by + lx] =
            __uint_as_float(f2tf(t[lx][ly + i]));
}

__global__ void round_v_kernel(float* __restrict__ kv) {
    int i = blockIdx.x * blockDim.x + threadIdx.x;   // float4 index
    if (i >= NTOK * 256) return;
    int n = i >> 8, c4 = i & 255;
    float4* p = (float4*)(kv + (size_t)n * 2048 + 1024 + c4 * 4);
    float4 v = *p;
    v.x = __uint_as_float(f2tf(v.x));
    v.y = __uint_as_float(f2tf(v.y));
    v.z = __uint_as_float(f2tf(v.z));
    v.w = __uint_as_float(f2tf(v.w));
    *p = v;
}

// ---------------------------------------------------------------------------
// RoPE (in place, writes rna-rounded)
// ---------------------------------------------------------------------------
__global__ void rope_kernel(float* __restrict__ buf, const float* __restrict__ rcos,
                            const float* __restrict__ rsin,
                            const int* __restrict__ positions,
                            int nheads, int rowstride) {
    int idx = blockIdx.x * blockDim.x + threadIdx.x;
    int total = NTOK * nheads * 64;
    if (idx >= total) return;
    int i = idx & 63;
    int h = (idx >> 6) % nheads;
    int n = idx / (64 * nheads);
    int pos = positions[n];
    float c = rcos[pos * 64 + i];
    float s = rsin[pos * 64 + i];
    float2* p = (float2*)(buf + (size_t)n * rowstride + h * 128 + 2 * i);
    float2 v = *p;
    float2 o;
    o.x = __uint_as_float(f2tf(v.x * c - v.y * s));
    o.y = __uint_as_float(f2tf(v.x * s + v.y * c));
    *p = o;
}

// ---------------------------------------------------------------------------
// Flash attention, causal, GQA, tf32 mma. All inputs pre-rounded to tf32.
// grid = (T/64, H, nb), block = 128 (4 warps). b = b_off + blockIdx.z.
// Longest causal tiles scheduled first. smem 101KB -> 2 CTAs/SM.
// ---------------------------------------------------------------------------
#define ATT_SMEM_FLOATS (3 * 64 * 132)

__global__ void __launch_bounds__(128)
attn_kernel(const float* __restrict__ q, const float* __restrict__ kv,
            float* __restrict__ out, int b_off) {
    extern __shared__ float sm[];
    float* Ks = sm;
    float* Vs = sm + 64 * 132;
    float* Qs = sm + 2 * 64 * 132;
    float* Ps = Qs;                    // alias: safe (per-warp rows)
    const uint32_t sK = smem_u32(Ks);
    const uint32_t sV = smem_u32(Vs);

    const int mblk = gridDim.x - 1 - blockIdx.x;   // longest tiles first
    const int m0  = mblk * 64;
    const int h   = blockIdx.y;
    const int b   = b_off + blockIdx.z;
    const int kvh = h >> 2;
    const int tid  = threadIdx.x;
    const int warp = tid >> 5;
    const int lane = tid & 31;
    const int gr = lane >> 2;
    const int tg = lane & 3;

    for (int i = tid; i < 64 * 32; i += 128) {
        int r = i >> 5, c4 = i & 31;
        float4 v = *(const float4*)&q[((size_t)(b * T_ + m0 + r) * H_ + h) * HD_ + c4 * 4];
        *(float4*)&Qs[r * 132 + c4 * 4] = v;
    }
    __syncthreads();

    uint32_t qf[16][4];
    #pragma unroll
    for (int ks = 0; ks < 16; ks++) {
        int r0 = warp * 16 + gr;
        int c0 = ks * 8 + tg;
        qf[ks][0] = __float_as_uint(Qs[r0 * 132 + c0]);
        qf[ks][1] = __float_as_uint(Qs[(r0 + 8) * 132 + c0]);
        qf[ks][2] = __float_as_uint(Qs[r0 * 132 + c0 + 4]);
        qf[ks][3] = __float_as_uint(Qs[(r0 + 8) * 132 + c0 + 4]);
    }

    float o_acc[16][4];
    #pragma unroll
    for (int nt = 0; nt < 16; nt++)
        #pragma unroll
        for (int e = 0; e < 4; e++) o_acc[nt][e] = 0.f;
    float m_i[2] = {-INFINITY, -INFINITY};
    float l_i[2] = {0.f, 0.f};

    const float scale = 0.08838834764831845f;
    const int ktiles = m0 / 64 + 1;

    for (int kt = 0; kt < ktiles; kt++) {
        int k0 = kt * 64;
        __syncthreads();
        {
            const float* base = &kv[(size_t)(b * T_ + k0) * 2048 + kvh * 128];
            #pragma unroll
            for (int p = 0; p < 16; p++) {
                int i = tid + p * 128;
                int r = i >> 5, c4 = i & 31;
                uint32_t soff = (uint32_t)(r * 132 + c4 * 4) * 4u;
                const float* kp = base + (size_t)r * 2048;
                cp_async16(sK + soff, kp + c4 * 4);
                cp_async16(sV + soff, kp + 1024 + c4 * 4);
            }
            CP_COMMIT();
            CP_WAIT(0);
        }
        __syncthreads();

        float s[8][4];
        #pragma unroll
        for (int nt = 0; nt < 8; nt++)
            #pragma unroll
            for (int e = 0; e < 4; e++) s[nt][e] = 0.f;

        #pragma unroll 4
        for (int ks = 0; ks < 16; ks++) {
            #pragma unroll
            for (int nt = 0; nt < 8; nt++) {
                int cc = nt * 8 + gr;
                int rr = ks * 8 + tg;
                uint32_t b0 = __float_as_uint(Ks[cc * 132 + rr]);
                uint32_t b1 = __float_as_uint(Ks[cc * 132 + rr + 4]);
                mma_tf32(s[nt], qf[ks], b0, b1);
            }
        }

        bool diag = (kt == ktiles - 1);
        #pragma unroll
        for (int nt = 0; nt < 8; nt++)
            #pragma unroll
            for (int e = 0; e < 4; e++) {
                int row = warp * 16 + gr + ((e >= 2) ? 8 : 0);
                int col = nt * 8 + 2 * tg + (e & 1);
                float v = s[nt][e] * scale;
                if (diag && (k0 + col > m0 + row)) v = -1e9f;
                s[nt][e] = v;
            }

        #pragma unroll
        for (int half = 0; half < 2; half++) {
            float mx = -INFINITY;
            #pragma unroll
            for (int nt = 0; nt < 8; nt++) {
                mx = fmaxf(mx, s[nt][half * 2]);
                mx = fmaxf(mx, s[nt][half * 2 + 1]);
            }
            mx = fmaxf(mx, __shfl_xor_sync(0xffffffffu, mx, 1));
            mx = fmaxf(mx, __shfl_xor_sync(0xffffffffu, mx, 2));
            float mnew = fmaxf(m_i[half], mx);
            float corr = __expf(m_i[half] - mnew);
            float lsum = 0.f;
            #pragma unroll
            for (int nt = 0; nt < 8; nt++) {
                float e0 = __expf(s[nt][half * 2]     - mnew);
                float e1 = __expf(s[nt][half * 2 + 1] - mnew);
                s[nt][half * 2]     = e0;
                s[nt][half * 2 + 1] = e1;
                lsum += e0 + e1;
            }
            lsum += __shfl_xor_sync(0xffffffffu, lsum, 1);
            lsum += __shfl_xor_sync(0xffffffffu, lsum, 2);
            m_i[half] = mnew;
            l_i[half] = l_i[half] * corr + lsum;
            #pragma unroll
            for (int nt = 0; nt < 16; nt++) {
                o_acc[nt][half * 2]     *= corr;
                o_acc[nt][half * 2 + 1] *= corr;
            }
        }

        #pragma unroll
        for (int nt = 0; nt < 8; nt++)
            #pragma unroll
            for (int e = 0; e < 4; e++) {
                int row = warp * 16 + gr + ((e >= 2) ? 8 : 0);
                int col = nt * 8 + 2 * tg + (e & 1);
                Ps[row * 132 + col] = __uint_as_float(f2tf(s[nt][e]));
            }
        __syncwarp();

        #pragma unroll
        for (int ks = 0; ks < 8; ks++) {
            uint32_t pa[4];
            int r0 = warp * 16 + gr;
            int c0 = ks * 8 + tg;
            pa[0] = __float_as_uint(Ps[r0 * 132 + c0]);
            pa[1] = __float_as_uint(Ps[(r0 + 8) * 132 + c0]);
            pa[2] = __float_as_uint(Ps[r0 * 132 + c0 + 4]);
            pa[3] = __float_as_uint(Ps[(r0 + 8) * 132 + c0 + 4]);
            #pragma unroll
            for (int nt = 0; nt < 16; nt++) {
                uint32_t b0 = __float_as_uint(Vs[(ks * 8 + tg) * 132 + nt * 8 + gr]);
                uint32_t b1 = __float_as_uint(Vs[(ks * 8 + tg + 4) * 132 + nt * 8 + gr]);
                mma_tf32(o_acc[nt], pa, b0, b1);
            }
        }
    }

    #pragma unroll
    for (int nt = 0; nt < 16; nt++)
        #pragma unroll
        for (int e = 0; e < 4; e++) {
            int row = warp * 16 + gr + ((e >= 2) ? 8 : 0);
            int col = nt * 8 + 2 * tg + (e & 1);
            float inv_l = 1.f / l_i[(e >= 2) ? 1 : 0];
            out[((size_t)(b * T_ + m0 + row) * H_ + h) * HD_ + col] =
                __uint_as_float(f2tf(o_acc[nt][e] * inv_l));
        }
}

// ---------------------------------------------------------------------------
// launch — R6-style fork (Q chain ∥ KV chain), then attn/O-GEMM split pipeline
// ---------------------------------------------------------------------------
extern "C" void kernel_launch(void* const* d_in, const int* in_sizes, int n_in,
                              void* d_out, int out_size) {
    const float* x    = (const float*)d_in[0];
    const float* w_q  = (const float*)d_in[1];
    const float* w_kv = (const float*)d_in[2];
    const float* w_o  = (const float*)d_in[3];
    const float* rcos = (const float*)d_in[6];
    const float* rsin = (const float*)d_in[7];
    const int* positions = (const int*)d_in[8];
    float* out = (float*)d_out;

    float *xb, *wqT, *wkvT, *woT, *qb, *kvb, *ab;
    cudaGetSymbolAddress((void**)&xb,   g_x);
    cudaGetSymbolAddress((void**)&wqT,  g_wqT);
    cudaGetSymbolAddress((void**)&wkvT, g_wkvT);
    cudaGetSymbolAddress((void**)&woT,  g_woT);
    cudaGetSymbolAddress((void**)&qb,   g_q);
    cudaGetSymbolAddress((void**)&kvb,  g_kv);
    cudaGetSymbolAddress((void**)&ab,   g_att);

    static cudaStream_t s1 = nullptr;
    static cudaEvent_t ev_start = nullptr, ev_rx = nullptr, ev_q = nullptr,
                       ev_wo = nullptr, ev_a0 = nullptr, ev_o0 = nullptr;
    if (s1 == nullptr) {
        cudaStreamCreateWithFlags(&s1, cudaStreamNonBlocking);
        cudaEventCreateWithFlags(&ev_start, cudaEventDisableTiming);
        cudaEventCreateWithFlags(&ev_rx,    cudaEventDisableTiming);
        cudaEventCreateWithFlags(&ev_q,     cudaEventDisableTiming);
        cudaEventCreateWithFlags(&ev_wo,    cudaEventDisableTiming);
        cudaEventCreateWithFlags(&ev_a0,    cudaEventDisableTiming);
        cudaEventCreateWithFlags(&ev_o0,    cudaEventDisableTiming);
        cudaFuncSetAttribute(gemm_tc,
            cudaFuncAttributeMaxDynamicSharedMemorySize, GEMM_SMEM);
        cudaFuncSetAttribute(attn_kernel,
            cudaFuncAttributeMaxDynamicSharedMemorySize, ATT_SMEM_FLOATS * 4);
    }

    // fork
    cudaEventRecord(ev_start, 0);
    cudaStreamWaitEvent(s1, ev_start, 0);

    // s0: round x, then KV chain
    round_x_kernel<<<(NTOK * DM_ / 4 + 255) / 256, 256>>>(x, xb, NTOK * DM_ / 4);
    cudaEventRecord(ev_rx, 0);
    transpose_rna_kernel<<<dim3(2048 / 32, DM_ / 32), dim3(32, 8)>>>(w_kv, wkvT, DM_, 2048);
    gemm_tc<<<dim3(2048 / BN, NTOK / BM), 256, GEMM_SMEM>>>(xb, wkvT, kvb, 2048);
    rope_kernel<<<(NTOK * KVH_ * 64) / 256, 256>>>(kvb, rcos, rsin, positions, KVH_, 2048);
    round_v_kernel<<<(NTOK * 256 + 255) / 256, 256>>>(kvb);

    // s1: Q chain (concurrent with KV chain) + w_o transpose
    transpose_rna_kernel<<<dim3(DM_ / 32, DM_ / 32), dim3(32, 8), 0, s1>>>(w_q, wqT, DM_, DM_);
    cudaStreamWaitEvent(s1, ev_rx, 0);
    gemm_tc<<<dim3(DM_ / BN, NTOK / BM), 256, GEMM_SMEM, s1>>>(xb, wqT, qb, DM_);
    rope_kernel<<<(NTOK * H_ * 64) / 256, 256, 0, s1>>>(qb, rcos, rsin, positions, H_, DM_);
    cudaEventRecord(ev_q, s1);
    transpose_rna_kernel<<<dim3(DM_ / 32, DM_ / 32), dim3(32, 8), 0, s1>>>(w_o, woT, DM_, DM_);
    cudaEventRecord(ev_wo, s1);

    // s0: attention half 0 (batches 0,1), then half 1 (batches 2,3)
    cudaStreamWaitEvent(0, ev_q, 0);
    attn_kernel<<<dim3(T_ / 64, H_, 2), 128, ATT_SMEM_FLOATS * 4>>>(qb, kvb, ab, 0);
    cudaEventRecord(ev_a0, 0);
    attn_kernel<<<dim3(T_ / 64, H_, 2), 128, ATT_SMEM_FLOATS * 4>>>(qb, kvb, ab, 2);

    // s1: O-projection half 0 (rows 0..2047) overlapping attention half 1
    cudaStreamWaitEvent(s1, ev_a0, 0);
    cudaStreamWaitEvent(s1, ev_wo, 0);
    gemm_tc<<<dim3(DM_ / BN, (NTOK / 2) / BM), 256, GEMM_SMEM, s1>>>(
        ab, woT, out, DM_);
    cudaEventRecord(ev_o0, s1);

    // s0: O-projection half 1 (rows 2048..4095), then join
    cudaStreamWaitEvent(0, ev_wo, 0);
    gemm_tc<<<dim3(DM_ / BN, (NTOK / 2) / BM), 256, GEMM_SMEM>>>(
        ab + (size_t)(NTOK / 2) * DM_, woT, out + (size_t)(NTOK / 2) * DM_, DM_);
    cudaStreamWaitEvent(0, ev_o0, 0);
}